// round 16
// baseline (speedup 1.0000x reference)
#include <cuda_runtime.h>
#include <math.h>

// ---------------- problem constants ----------------
#define BB    8
#define NN    8192
#define SS    2048
#define KK    32
#define CPTS  64
#define MM    (BB*SS*KK)            // 524288 rows
#define OUT_XYZ_ELEMS (BB*SS*3)     // 49152 floats of new_xyz at front of output

typedef unsigned long long u64;

// ---------------- device scratch ----------------
__device__ int    g_ballidx[MM];
__device__ float  g_x0[(size_t)MM*64];
__device__ float  g_x1[(size_t)MM*64];
__device__ float2 g_pool2[(size_t)BB*SS*128];
__device__ double g_sum[128];      // zero-init at load; k_finalize re-zeroes
__device__ double g_sumsq[128];
__device__ float  g_aff_a[128];
__device__ float  g_aff_c[128];

// ---------------- packed f32x2 helpers ----------------
__device__ __forceinline__ u64 pack2(float lo, float hi){
    u64 r; asm("mov.b64 %0, {%1, %2};" : "=l"(r) : "f"(lo), "f"(hi)); return r;
}
__device__ __forceinline__ u64 dup2(float v){
    u64 r; asm("mov.b64 %0, {%1, %1};" : "=l"(r) : "f"(v)); return r;
}
__device__ __forceinline__ void unpack2(u64 v, float& lo, float& hi){
    asm("mov.b64 {%0, %1}, %2;" : "=f"(lo), "=f"(hi) : "l"(v));
}
__device__ __forceinline__ u64 add2(u64 a, u64 b){
    u64 r; asm("add.rn.f32x2 %0, %1, %2;" : "=l"(r) : "l"(a), "l"(b)); return r;
}
__device__ __forceinline__ u64 mul2(u64 a, u64 b){
    u64 r; asm("mul.rn.f32x2 %0, %1, %2;" : "=l"(r) : "l"(a), "l"(b)); return r;
}
__device__ __forceinline__ u64 fma2(u64 a, u64 b, u64 c){
    u64 r; asm("fma.rn.f32x2 %0, %1, %2, %3;" : "=l"(r) : "l"(a), "l"(b), "l"(c)); return r;
}

// =====================================================================
// 1) FPS with PER-THREAD ballot pruning (lexicographic bucket sort).
//    256 threads/batch, 32 pts/thread, each thread's points CONTIGUOUS in
//    sorted order -> tight per-thread micro-bbox. A warp skips its whole
//    update iff EVERY thread's test fires:
//        dmin2(c, bbox_t) * (1-1e-5) > ub_t   (ub_t = thread's max md)
//    which provably (fp margin) cannot change any md -> bit-exact.
//    md as u32 float-bits; tie-break = min ORIGINAL index among maxes.
// =====================================================================
#define FPS_THR 256
__global__ void __launch_bounds__(FPS_THR,1) k_fps(const float* __restrict__ xyz,
                                                   float* __restrict__ out)
{
    extern __shared__ __align__(16) unsigned char smraw[];
    float*  sxs   = (float*)smraw;                         // 8192
    float*  sys   = sxs + NN;                              // 8192
    float*  szs   = sys + NN;                              // 8192
    unsigned short* s_fwd = (unsigned short*)(szs + NN);   // 8192 (sortedpos->orig)
    unsigned short* s_inv = s_fwd + NN;                    // 8192 (orig->sortedpos)
    int*      s_hist = (int*)(s_inv + NN);                 // 512
    unsigned* sdist  = (unsigned*)(s_hist + 512);          // 64 (2x32 parity)
    unsigned* sidx   = sdist + 64;                         // 64
    float*    smm    = (float*)(sidx + 64);                // 48 (8 warps x 6)

    int b = blockIdx.x;
    const float* X = xyz + (size_t)b*NN*3;
    int t = threadIdx.x, lane = t & 31, wid = t >> 5;   // wid 0..7

    // ---------------- prologue: load + global min/max + bucket sort ----
    float px[32], py[32], pz[32];
    {
        float mnx=1e30f,mxx=-1e30f,mny=1e30f,mxy=-1e30f,mnz=1e30f,mxz=-1e30f;
#pragma unroll
        for (int i=0;i<32;i++){
            int j = i*256 + t;
            px[i]=X[j*3+0]; py[i]=X[j*3+1]; pz[i]=X[j*3+2];
            mnx=fminf(mnx,px[i]); mxx=fmaxf(mxx,px[i]);
            mny=fminf(mny,py[i]); mxy=fmaxf(mxy,py[i]);
            mnz=fminf(mnz,pz[i]); mxz=fmaxf(mxz,pz[i]);
        }
#pragma unroll
        for (int off=16; off>0; off>>=1){
            mnx=fminf(mnx,__shfl_xor_sync(0xffffffffu,mnx,off));
            mxx=fmaxf(mxx,__shfl_xor_sync(0xffffffffu,mxx,off));
            mny=fminf(mny,__shfl_xor_sync(0xffffffffu,mny,off));
            mxy=fmaxf(mxy,__shfl_xor_sync(0xffffffffu,mxy,off));
            mnz=fminf(mnz,__shfl_xor_sync(0xffffffffu,mnz,off));
            mxz=fmaxf(mxz,__shfl_xor_sync(0xffffffffu,mxz,off));
        }
        if (lane==0){
            smm[wid*6+0]=mnx; smm[wid*6+1]=mxx;
            smm[wid*6+2]=mny; smm[wid*6+3]=mxy;
            smm[wid*6+4]=mnz; smm[wid*6+5]=mxz;
        }
        s_hist[t]=0; s_hist[t+256]=0;
    }
    __syncthreads();

    float gmnx=smm[0],gmxx=smm[1],gmny=smm[2],gmxy=smm[3],gmnz=smm[4],gmxz=smm[5];
#pragma unroll
    for (int w=1;w<8;w++){
        gmnx=fminf(gmnx,smm[w*6+0]); gmxx=fmaxf(gmxx,smm[w*6+1]);
        gmny=fminf(gmny,smm[w*6+2]); gmxy=fmaxf(gmxy,smm[w*6+3]);
        gmnz=fminf(gmnz,smm[w*6+4]); gmxz=fmaxf(gmxz,smm[w*6+5]);
    }
    float rx=gmxx-gmnx, ry=gmxy-gmny, rz=gmxz-gmnz;
    float sclx = (rx>0.f)? 7.9375f/rx : 0.f;
    float scly = (ry>0.f)? 7.9375f/ry : 0.f;
    float sclz = (rz>0.f)? 7.9375f/rz : 0.f;

#pragma unroll
    for (int i=0;i<32;i++){
        int cxq=(int)((px[i]-gmnx)*sclx);
        int cyq=(int)((py[i]-gmny)*scly);
        int czq=(int)((pz[i]-gmnz)*sclz);
        int cell=(cxq<<6)|(cyq<<3)|czq;
        atomicAdd(&s_hist[cell],1);
    }
    __syncthreads();

    // exclusive prefix over 512 bins by warp 0
    if (t < 32){
        int v[16]; int run=0;
#pragma unroll
        for (int k2=0;k2<16;k2++) v[k2]=s_hist[t*16+k2];
#pragma unroll
        for (int k2=0;k2<16;k2++){ int c=v[k2]; v[k2]=run; run+=c; }
        int inc = run;
#pragma unroll
        for (int off=1; off<32; off<<=1){
            int o=__shfl_up_sync(0xffffffffu, inc, off);
            if (lane >= off) inc += o;
        }
        int excl = inc - run;
#pragma unroll
        for (int k2=0;k2<16;k2++) s_hist[t*16+k2]=v[k2]+excl;
    }
    __syncthreads();

    // scatter into sorted arrays
#pragma unroll
    for (int i=0;i<32;i++){
        int cxq=(int)((px[i]-gmnx)*sclx);
        int cyq=(int)((py[i]-gmny)*scly);
        int czq=(int)((pz[i]-gmnz)*sclz);
        int cell=(cxq<<6)|(cyq<<3)|czq;
        int pos = atomicAdd(&s_hist[cell],1);
        sxs[pos]=px[i]; sys[pos]=py[i]; szs[pos]=pz[i];
        int oj = i*256 + t;
        s_fwd[pos]=(unsigned short)oj;
        s_inv[oj]=(unsigned short)pos;
    }
    __syncthreads();

    // reload sorted slab: thread owns positions t*32..t*32+31 (contiguous!)
    u64 cx[16], cy[16], cz[16];
    unsigned oi[16];
    unsigned md[32];
    const unsigned MD_INIT = __float_as_uint(1e10f);
    float bmnx=1e30f,bmxx=-1e30f,bmny=1e30f,bmxy=-1e30f,bmnz=1e30f,bmxz=-1e30f;
#pragma unroll
    for (int q=0;q<16;q++){
        int p0 = t*32 + 2*q;
        float x0=sxs[p0], x1=sxs[p0+1];
        float y0=sys[p0], y1=sys[p0+1];
        float z0=szs[p0], z1=szs[p0+1];
        cx[q]=pack2(x0,x1); cy[q]=pack2(y0,y1); cz[q]=pack2(z0,z1);
        unsigned lo=s_fwd[p0], hi=s_fwd[p0+1];
        oi[q] = lo | (hi<<16);
        md[2*q]=MD_INIT; md[2*q+1]=MD_INIT;
        bmnx=fminf(bmnx,fminf(x0,x1)); bmxx=fmaxf(bmxx,fmaxf(x0,x1));
        bmny=fminf(bmny,fminf(y0,y1)); bmxy=fmaxf(bmxy,fmaxf(y0,y1));
        bmnz=fminf(bmnz,fminf(z0,z1)); bmxz=fmaxf(bmxz,fmaxf(z0,z1));
    }
    // NOTE: bbox stays PER-THREAD (no warp reduce) -> tight micro-bbox.
    if (t < 64){
        int half = t >> 5, slot = t & 31;
        if (slot >= 8){
            sdist[half*32 + slot] = 0u;
            sidx [half*32 + slot] = 0xffffffffu;
        }
    }
    unsigned ub_t        = MD_INIT;    // thread's max md (cached)
    unsigned cached_rmax = MD_INIT;    // warp winner (cached)
    unsigned cached_jw   = 0u;
    __syncthreads();

    float lx=X[0], ly=X[1], lz=X[2];
    float* onew = out + (size_t)b*SS*3;

    for (int s=0;s<SS;s++){
        if (t==0){ onew[s*3+0]=lx; onew[s*3+1]=ly; onew[s*3+2]=lz; }

        // per-thread micro-bbox test; warp skips iff ALL threads prune
        float ddx = fmaxf(fmaxf(bmnx-lx, lx-bmxx), 0.0f);
        float ddy = fmaxf(fmaxf(bmny-ly, ly-bmxy), 0.0f);
        float ddz = fmaxf(fmaxf(bmnz-lz, lz-bmxz), 0.0f);
        float dmin2 = __fmaf_rn(ddx,ddx,__fmaf_rn(ddy,ddy,__fmul_rn(ddz,ddz)));
        bool prune_t = (dmin2 * 0.99999f > __uint_as_float(ub_t));
        unsigned ball = __ballot_sync(0xffffffffu, prune_t);
        bool doupd = (ball != 0xffffffffu);

        unsigned rmax_w, jwor;
        if (doupd){
            u64 nlx=dup2(-lx), nly=dup2(-ly), nlz=dup2(-lz);
#pragma unroll
            for (int q=0;q<16;q++){
                u64 dx=add2(cx[q],nlx);
                u64 dy=add2(cy[q],nly);
                u64 dz=add2(cz[q],nlz);
                u64 dd=fma2(dz,dz,fma2(dy,dy,mul2(dx,dx)));
                float d0,d1; unpack2(dd,d0,d1);
                md[2*q]   = umin(md[2*q],   __float_as_uint(d0));
                md[2*q+1] = umin(md[2*q+1], __float_as_uint(d1));
            }
            unsigned g2_[16];
#pragma unroll
            for (int i=0;i<16;i++) g2_[i]=umax(md[2*i],md[2*i+1]);
            unsigned g4_[8];
#pragma unroll
            for (int i=0;i<8;i++) g4_[i]=umax(g2_[2*i],g2_[2*i+1]);
            unsigned g8a=umax(g4_[0],g4_[1]), g8b=umax(g4_[2],g4_[3]);
            unsigned g8c=umax(g4_[4],g4_[5]), g8d=umax(g4_[6],g4_[7]);
            unsigned bvu=umax(umax(g8a,g8b),umax(g8c,g8d));
            ub_t = bvu;

            unsigned m8[8];
#pragma unroll
            for (int q=0;q<16;q+=2){
                unsigned lo0=oi[q]&0xffffu,   hi0=oi[q]>>16;
                unsigned lo1=oi[q+1]&0xffffu, hi1=oi[q+1]>>16;
                unsigned a=(md[2*q]==bvu)  ? lo0 : 0xffffu;
                unsigned bq=(md[2*q+1]==bvu)? hi0 : 0xffffu;
                unsigned c=(md[2*q+2]==bvu)? lo1 : 0xffffu;
                unsigned d=(md[2*q+3]==bvu)? hi1 : 0xffffu;
                m8[q>>1]=umin(umin(a,bq),umin(c,d));
            }
            unsigned mo = umin(umin(umin(m8[0],m8[1]),umin(m8[2],m8[3])),
                               umin(umin(m8[4],m8[5]),umin(m8[6],m8[7])));

            rmax_w = __reduce_max_sync(0xffffffffu, bvu);
            unsigned cand = (bvu==rmax_w) ? mo : 0xffffffffu;
            jwor   = __reduce_min_sync(0xffffffffu, cand);
            cached_rmax = rmax_w; cached_jw = jwor;
        } else {
            rmax_w = cached_rmax; jwor = cached_jw;
        }

        int pb = (s & 1) * 32;
        if (lane==0){ sdist[pb + wid] = rmax_w; sidx[pb + wid] = jwor; }
        __syncthreads();

        unsigned d2v = sdist[pb + lane];
        unsigned i2v = sidx [pb + lane];
        unsigned gmax = __reduce_max_sync(0xffffffffu, d2v);
        unsigned c2   = (d2v==gmax) ? i2v : 0xffffffffu;
        unsigned jo   = __reduce_min_sync(0xffffffffu, c2);

        int pos = (int)s_inv[jo];
        lx = sxs[pos]; ly = sys[pos]; lz = szs[pos];
    }
}

// =====================================================================
// 2) Ball query (unchanged)
// =====================================================================
__global__ void __launch_bounds__(256,1) k_ballq(const float* __restrict__ xyz,
                                                 const float* __restrict__ newxyz)
{
    extern __shared__ __align__(16) unsigned char s_raw[];
    float4* sp = (float4*)s_raw;

    int b     = blockIdx.x >> 5;
    int sbase = (blockIdx.x & 31) * 64;
    const float* X = xyz + (size_t)b*NN*3;

    for (int j=threadIdx.x; j<NN; j+=256){
        float x=X[j*3+0], y=X[j*3+1], z=X[j*3+2];
        float pp=__fmaf_rn(z,z,__fmaf_rn(y,y,__fmul_rn(x,x)));
        sp[j]=make_float4(x,y,z,pp);
    }
    __syncthreads();

    int wid=threadIdx.x>>5, lane=threadIdx.x&31;
    for (int ci=0; ci<8; ci++){
        int s = sbase + wid*8 + ci;
        const float* q = newxyz + ((size_t)b*SS + s)*3;
        float qx=q[0], qy=q[1], qz=q[2];
        float qq=__fmaf_rn(qz,qz,__fmaf_rn(qy,qy,__fmul_rn(qx,qx)));
        int* o = g_ballidx + ((size_t)b*SS + s)*KK;
        int cnt=0, first=0; bool havefirst=false;

        for (int base=0; base<NN; base+=32){
            float4 p = sp[base+lane];
            float dot=__fmaf_rn(qz,p.z,__fmaf_rn(qy,p.y,__fmul_rn(qx,p.x)));
            float d2 =__fmaf_rn(-2.0f,dot,__fadd_rn(qq,p.w));
            bool valid = (d2 <= 0.0625f);
            unsigned m = __ballot_sync(0xffffffffu, valid);
            if (m){
                if (!havefirst){ first = base + (__ffs(m)-1); havefirst=true; }
                int pre = __popc(m & ((1u<<lane)-1u));
                if (valid && (cnt+pre) < KK) o[cnt+pre] = base+lane;
                cnt += __popc(m);
                if (cnt >= KK) break;
            }
        }
        if (cnt < KK){
            for (int p=cnt+lane; p<KK; p+=32) o[p]=first;
        }
    }
}

// =====================================================================
// 3) stats finalize
// =====================================================================
__global__ void k_finalize(const float* __restrict__ g, const float* __restrict__ be, int C)
{
    int c = threadIdx.x;
    if (c < C){
        double mean = g_sum[c]   * (1.0/(double)MM);
        double var  = g_sumsq[c] * (1.0/(double)MM) - mean*mean;
        double a = (double)g[c] / sqrt(var + 1e-5);
        g_aff_a[c] = (float)a;
        g_aff_c[c] = (float)((double)be[c] - mean*a);
        g_sum[c]=0.0; g_sumsq[c]=0.0;
    }
}

// =====================================================================
// 4) layer 0: gather + GEMM [128 rows x 64 cols], K=67, f32x2 row-pair packed.
// =====================================================================
__global__ void __launch_bounds__(128) k_layer0(const float* __restrict__ xyz,
                                                const float* __restrict__ pts,
                                                const float* __restrict__ newxyz,
                                                const float* __restrict__ w0,
                                                const float* __restrict__ b0)
{
    extern __shared__ __align__(16) unsigned char s_raw[];
    u64*   sfP = (u64*)s_raw;                       // [67][64] pairs, k-major
    float* sw  = (float*)(s_raw + 67*64*8);         // [67][64] k-major
    int t = threadIdx.x;
    size_t row0 = (size_t)blockIdx.x * 128;

    for (int i=t; i<67*64; i+=128){
        int o = i/67, c = i%67;
        int cp = (c>=3) ? (c-3) : (64+c);
        sw[cp*64+o] = w0[i];
    }
    {
        int p = t & 63, h = t >> 6;
        size_t r0g = row0 + 2*p, r1g = r0g + 1;
        int bs = (int)(r0g >> 5);
        int b  = bs >> 11;
        int n0 = g_ballidx[r0g], n1 = g_ballidx[r1g];
        const float4* ra = (const float4*)(pts + ((size_t)b*NN + n0)*CPTS) + h*8;
        const float4* rb = (const float4*)(pts + ((size_t)b*NN + n1)*CPTS) + h*8;
        int c0 = h*32;
#pragma unroll
        for (int v=0; v<8; v++){
            float4 a = ra[v], b4 = rb[v];
            int c = c0 + v*4;
            sfP[(c+0)*64+p]=pack2(a.x,b4.x);
            sfP[(c+1)*64+p]=pack2(a.y,b4.y);
            sfP[(c+2)*64+p]=pack2(a.z,b4.z);
            sfP[(c+3)*64+p]=pack2(a.w,b4.w);
        }
        if (h==0){
            const float* p3a = xyz + ((size_t)b*NN + n0)*3;
            const float* p3b = xyz + ((size_t)b*NN + n1)*3;
            const float* c3  = newxyz + (size_t)bs*3;
            sfP[64*64+p]=pack2(p3a[0]-c3[0], p3b[0]-c3[0]);
            sfP[65*64+p]=pack2(p3a[1]-c3[1], p3b[1]-c3[1]);
            sfP[66*64+p]=pack2(p3a[2]-c3[2], p3b[2]-c3[2]);
        }
    }
    __syncthreads();

    int tx = t & 7, tp = t >> 3;
    u64 acc[4][8];
#pragma unroll
    for (int i=0;i<4;i++)
#pragma unroll
        for (int j=0;j<8;j++) acc[i][j]=0ull;

    for (int k=0;k<64;k+=4){
#pragma unroll
        for (int kk=0;kk<4;kk++){
            const u64* arow = sfP + (size_t)(k+kk)*64 + tp*4;
            ulonglong2 v0 = *(const ulonglong2*)arow;
            ulonglong2 v1 = *(const ulonglong2*)(arow+2);
            const float4* brow = (const float4*)(sw + (size_t)(k+kk)*64 + tx*8);
            float4 b0v=brow[0], b1v=brow[1];
            u64 bb[8];
            bb[0]=dup2(b0v.x); bb[1]=dup2(b0v.y); bb[2]=dup2(b0v.z); bb[3]=dup2(b0v.w);
            bb[4]=dup2(b1v.x); bb[5]=dup2(b1v.y); bb[6]=dup2(b1v.z); bb[7]=dup2(b1v.w);
            u64 a0=v0.x,a1=v0.y,a2=v1.x,a3=v1.y;
#pragma unroll
            for (int j=0;j<8;j++){
                acc[0][j]=fma2(a0,bb[j],acc[0][j]);
                acc[1][j]=fma2(a1,bb[j],acc[1][j]);
                acc[2][j]=fma2(a2,bb[j],acc[2][j]);
                acc[3][j]=fma2(a3,bb[j],acc[3][j]);
            }
        }
    }
#pragma unroll
    for (int k=64;k<67;k++){
        const u64* arow = sfP + (size_t)k*64 + tp*4;
        ulonglong2 v0 = *(const ulonglong2*)arow;
        ulonglong2 v1 = *(const ulonglong2*)(arow+2);
        const float4* brow = (const float4*)(sw + (size_t)k*64 + tx*8);
        float4 b0v=brow[0], b1v=brow[1];
        u64 bb[8];
        bb[0]=dup2(b0v.x); bb[1]=dup2(b0v.y); bb[2]=dup2(b0v.z); bb[3]=dup2(b0v.w);
        bb[4]=dup2(b1v.x); bb[5]=dup2(b1v.y); bb[6]=dup2(b1v.z); bb[7]=dup2(b1v.w);
        u64 a0=v0.x,a1=v0.y,a2=v1.x,a3=v1.y;
#pragma unroll
        for (int j=0;j<8;j++){
            acc[0][j]=fma2(a0,bb[j],acc[0][j]);
            acc[1][j]=fma2(a1,bb[j],acc[1][j]);
            acc[2][j]=fma2(a2,bb[j],acc[2][j]);
            acc[3][j]=fma2(a3,bb[j],acc[3][j]);
        }
    }

    u64 bP[8];
    {
        float4 b0v = *(const float4*)&b0[tx*8];
        float4 b1v = *(const float4*)&b0[tx*8+4];
        bP[0]=dup2(b0v.x); bP[1]=dup2(b0v.y); bP[2]=dup2(b0v.z); bP[3]=dup2(b0v.w);
        bP[4]=dup2(b1v.x); bP[5]=dup2(b1v.y); bP[6]=dup2(b1v.z); bP[7]=dup2(b1v.w);
    }
    float s1[8], s2[8];
#pragma unroll
    for (int j=0;j<8;j++){ s1[j]=0.f; s2[j]=0.f; }
#pragma unroll
    for (int i=0;i<4;i++){
        size_t ra = row0 + (size_t)(tp*4+i)*2;
        float lo[8], hi[8];
#pragma unroll
        for (int j=0;j<8;j++){
            u64 v = add2(acc[i][j], bP[j]);
            unpack2(v, lo[j], hi[j]);
            s1[j]+=lo[j]; s1[j]+=hi[j];
            s2[j]=fmaf(lo[j],lo[j],s2[j]); s2[j]=fmaf(hi[j],hi[j],s2[j]);
        }
        *(float4*)&g_x0[ra*64 + tx*8]       = make_float4(lo[0],lo[1],lo[2],lo[3]);
        *(float4*)&g_x0[ra*64 + tx*8 + 4]   = make_float4(lo[4],lo[5],lo[6],lo[7]);
        *(float4*)&g_x0[(ra+1)*64 + tx*8]   = make_float4(hi[0],hi[1],hi[2],hi[3]);
        *(float4*)&g_x0[(ra+1)*64 + tx*8+4] = make_float4(hi[4],hi[5],hi[6],hi[7]);
    }
    __syncthreads();
    float2* part = (float2*)s_raw;   // [16][64]
#pragma unroll
    for (int j=0;j<8;j++) part[tp*64 + tx*8 + j] = make_float2(s1[j], s2[j]);
    __syncthreads();
    if (t < 64){
        float ss1=0.f, ss2=0.f;
#pragma unroll
        for (int r=0;r<16;r++){ float2 v = part[r*64+t]; ss1+=v.x; ss2+=v.y; }
        atomicAdd(&g_sum[t],   (double)ss1);
        atomicAdd(&g_sumsq[t], (double)ss2);
    }
}

// =====================================================================
// 5) layer 1: relu(affine(x0)) @ W^T + b, 128x64 tile, f32x2 packed
// =====================================================================
__global__ void __launch_bounds__(128) k_layer1(const float* __restrict__ xin,
                                                const float* __restrict__ w,
                                                const float* __restrict__ bias,
                                                float* __restrict__ xout)
{
    extern __shared__ __align__(16) unsigned char s_raw[];
    u64*   sfP = (u64*)s_raw;                       // [64][64]
    float* sw  = (float*)(s_raw + 64*64*8);         // [64][64]
    int t = threadIdx.x;
    size_t row0 = (size_t)blockIdx.x * 128;

    for (int i=t; i<64*64; i+=128){
        int o=i>>6, c=i&63;
        sw[c*64+o] = w[i];
    }
    {
        int p = t & 63, h = t >> 6;
        const float4* ra = (const float4*)(xin + (row0 + 2*p)*64) + h*8;
        const float4* rb = (const float4*)(xin + (row0 + 2*p+1)*64) + h*8;
        int c0 = h*32;
#pragma unroll
        for (int v=0; v<8; v++){
            float4 a = ra[v], b4 = rb[v];
            int c = c0 + v*4;
            float a0=fmaxf(fmaf(a.x, g_aff_a[c+0], g_aff_c[c+0]),0.f);
            float a1=fmaxf(fmaf(a.y, g_aff_a[c+1], g_aff_c[c+1]),0.f);
            float a2=fmaxf(fmaf(a.z, g_aff_a[c+2], g_aff_c[c+2]),0.f);
            float a3=fmaxf(fmaf(a.w, g_aff_a[c+3], g_aff_c[c+3]),0.f);
            float b0=fmaxf(fmaf(b4.x,g_aff_a[c+0], g_aff_c[c+0]),0.f);
            float b1=fmaxf(fmaf(b4.y,g_aff_a[c+1], g_aff_c[c+1]),0.f);
            float b2=fmaxf(fmaf(b4.z,g_aff_a[c+2], g_aff_c[c+2]),0.f);
            float b3=fmaxf(fmaf(b4.w,g_aff_a[c+3], g_aff_c[c+3]),0.f);
            sfP[(c+0)*64+p]=pack2(a0,b0);
            sfP[(c+1)*64+p]=pack2(a1,b1);
            sfP[(c+2)*64+p]=pack2(a2,b2);
            sfP[(c+3)*64+p]=pack2(a3,b3);
        }
    }
    __syncthreads();

    int tx = t & 7, tp = t >> 3;
    u64 acc[4][8];
#pragma unroll
    for (int i=0;i<4;i++)
#pragma unroll
        for (int j=0;j<8;j++) acc[i][j]=0ull;

    for (int k=0;k<64;k+=4){
#pragma unroll
        for (int kk=0;kk<4;kk++){
            const u64* arow = sfP + (size_t)(k+kk)*64 + tp*4;
            ulonglong2 v0 = *(const ulonglong2*)arow;
            ulonglong2 v1 = *(const ulonglong2*)(arow+2);
            const float4* brow = (const float4*)(sw + (size_t)(k+kk)*64 + tx*8);
            float4 b0v=brow[0], b1v=brow[1];
            u64 bb[8];
            bb[0]=dup2(b0v.x); bb[1]=dup2(b0v.y); bb[2]=dup2(b0v.z); bb[3]=dup2(b0v.w);
            bb[4]=dup2(b1v.x); bb[5]=dup2(b1v.y); bb[6]=dup2(b1v.z); bb[7]=dup2(b1v.w);
            u64 a0=v0.x,a1=v0.y,a2=v1.x,a3=v1.y;
#pragma unroll
            for (int j=0;j<8;j++){
                acc[0][j]=fma2(a0,bb[j],acc[0][j]);
                acc[1][j]=fma2(a1,bb[j],acc[1][j]);
                acc[2][j]=fma2(a2,bb[j],acc[2][j]);
                acc[3][j]=fma2(a3,bb[j],acc[3][j]);
            }
        }
    }

    u64 bP[8];
    {
        float4 b0v = *(const float4*)&bias[tx*8];
        float4 b1v = *(const float4*)&bias[tx*8+4];
        bP[0]=dup2(b0v.x); bP[1]=dup2(b0v.y); bP[2]=dup2(b0v.z); bP[3]=dup2(b0v.w);
        bP[4]=dup2(b1v.x); bP[5]=dup2(b1v.y); bP[6]=dup2(b1v.z); bP[7]=dup2(b1v.w);
    }
    float s1[8], s2[8];
#pragma unroll
    for (int j=0;j<8;j++){ s1[j]=0.f; s2[j]=0.f; }
#pragma unroll
    for (int i=0;i<4;i++){
        size_t ra = row0 + (size_t)(tp*4+i)*2;
        float lo[8], hi[8];
#pragma unroll
        for (int j=0;j<8;j++){
            u64 v = add2(acc[i][j], bP[j]);
            unpack2(v, lo[j], hi[j]);
            s1[j]+=lo[j]; s1[j]+=hi[j];
            s2[j]=fmaf(lo[j],lo[j],s2[j]); s2[j]=fmaf(hi[j],hi[j],s2[j]);
        }
        *(float4*)&xout[ra*64 + tx*8]       = make_float4(lo[0],lo[1],lo[2],lo[3]);
        *(float4*)&xout[ra*64 + tx*8 + 4]   = make_float4(lo[4],lo[5],lo[6],lo[7]);
        *(float4*)&xout[(ra+1)*64 + tx*8]   = make_float4(hi[0],hi[1],hi[2],hi[3]);
        *(float4*)&xout[(ra+1)*64 + tx*8+4] = make_float4(hi[4],hi[5],hi[6],hi[7]);
    }
    __syncthreads();
    float2* part = (float2*)s_raw;
#pragma unroll
    for (int j=0;j<8;j++) part[tp*64 + tx*8 + j] = make_float2(s1[j], s2[j]);
    __syncthreads();
    if (t < 64){
        float ss1=0.f, ss2=0.f;
#pragma unroll
        for (int r=0;r<16;r++){ float2 v = part[r*64+t]; ss1+=v.x; ss2+=v.y; }
        atomicAdd(&g_sum[t],   (double)ss1);
        atomicAdd(&g_sumsq[t], (double)ss2);
    }
}

// =====================================================================
// 6) layer 2: relu(affine(x1)) @ W^T + b, 128x128 tile, f32x2 packed.
// =====================================================================
__global__ void __launch_bounds__(256) k_layer2(const float* __restrict__ xin,
                                                const float* __restrict__ w,
                                                const float* __restrict__ bias)
{
    extern __shared__ __align__(16) unsigned char s_raw[];
    u64*   sfP = (u64*)s_raw;                       // [64][64]  32KB
    float* sw  = (float*)(s_raw + 64*64*8);         // [64][128] 32KB
    int t = threadIdx.x;
    size_t row0 = (size_t)blockIdx.x * 128;

    for (int i=t; i<128*64; i+=256){
        int o=i>>6, c=i&63;
        sw[c*128+o] = w[i];
    }
    {
        int p = t & 63, q = t >> 6;
        const float4* ra = (const float4*)(xin + (row0 + 2*p)*64) + q*4;
        const float4* rb = (const float4*)(xin + (row0 + 2*p+1)*64) + q*4;
        int c0 = q*16;
#pragma unroll
        for (int v=0; v<4; v++){
            float4 a = ra[v], b4 = rb[v];
            int c = c0 + v*4;
            float a0=fmaxf(fmaf(a.x, g_aff_a[c+0], g_aff_c[c+0]),0.f);
            float a1=fmaxf(fmaf(a.y, g_aff_a[c+1], g_aff_c[c+1]),0.f);
            float a2=fmaxf(fmaf(a.z, g_aff_a[c+2], g_aff_c[c+2]),0.f);
            float a3=fmaxf(fmaf(a.w, g_aff_a[c+3], g_aff_c[c+3]),0.f);
            float b0=fmaxf(fmaf(b4.x,g_aff_a[c+0], g_aff_c[c+0]),0.f);
            float b1=fmaxf(fmaf(b4.y,g_aff_a[c+1], g_aff_c[c+1]),0.f);
            float b2=fmaxf(fmaf(b4.z,g_aff_a[c+2], g_aff_c[c+2]),0.f);
            float b3=fmaxf(fmaf(b4.w,g_aff_a[c+3], g_aff_c[c+3]),0.f);
            sfP[(c+0)*64+p]=pack2(a0,b0);
            sfP[(c+1)*64+p]=pack2(a1,b1);
            sfP[(c+2)*64+p]=pack2(a2,b2);
            sfP[(c+3)*64+p]=pack2(a3,b3);
        }
    }
    __syncthreads();

    int tx = t & 15, tp = t >> 4;
    u64 acc[4][8];
#pragma unroll
    for (int i=0;i<4;i++)
#pragma unroll
        for (int j=0;j<8;j++) acc[i][j]=0ull;

    for (int k=0;k<64;k+=4){
#pragma unroll
        for (int kk=0;kk<4;kk++){
            const u64* arow = sfP + (size_t)(k+kk)*64 + tp*4;
            ulonglong2 v0 = *(const ulonglong2*)arow;
            ulonglong2 v1 = *(const ulonglong2*)(arow+2);
            const float4* brow = (const float4*)(sw + (size_t)(k+kk)*128 + tx*8);
            float4 b0v=brow[0], b1v=brow[1];
            u64 bb[8];
            bb[0]=dup2(b0v.x); bb[1]=dup2(b0v.y); bb[2]=dup2(b0v.z); bb[3]=dup2(b0v.w);
            bb[4]=dup2(b1v.x); bb[5]=dup2(b1v.y); bb[6]=dup2(b1v.z); bb[7]=dup2(b1v.w);
            u64 a0=v0.x,a1=v0.y,a2=v1.x,a3=v1.y;
#pragma unroll
            for (int j=0;j<8;j++){
                acc[0][j]=fma2(a0,bb[j],acc[0][j]);
                acc[1][j]=fma2(a1,bb[j],acc[1][j]);
                acc[2][j]=fma2(a2,bb[j],acc[2][j]);
                acc[3][j]=fma2(a3,bb[j],acc[3][j]);
            }
        }
    }

    u64 bP[8];
    {
        float4 b0v = *(const float4*)&bias[tx*8];
        float4 b1v = *(const float4*)&bias[tx*8+4];
        bP[0]=dup2(b0v.x); bP[1]=dup2(b0v.y); bP[2]=dup2(b0v.z); bP[3]=dup2(b0v.w);
        bP[4]=dup2(b1v.x); bP[5]=dup2(b1v.y); bP[6]=dup2(b1v.z); bP[7]=dup2(b1v.w);
    }
    float s1[8], s2[8], mx[8], mn[8];
#pragma unroll
    for (int j=0;j<8;j++){ s1[j]=0.f; s2[j]=0.f; mx[j]=-3.4e38f; mn[j]=3.4e38f; }
#pragma unroll
    for (int i=0;i<4;i++){
#pragma unroll
        for (int j=0;j<8;j++){
            u64 v = add2(acc[i][j], bP[j]);
            float lo, hi; unpack2(v, lo, hi);
            s1[j]+=lo; s1[j]+=hi;
            s2[j]=fmaf(lo,lo,s2[j]); s2[j]=fmaf(hi,hi,s2[j]);
            mx[j]=fmaxf(mx[j], fmaxf(lo,hi));
            mn[j]=fminf(mn[j], fminf(lo,hi));
        }
    }
    __syncthreads();
    float4* part = (float4*)s_raw;   // [16][128] = 32KB
#pragma unroll
    for (int j=0;j<8;j++) part[tp*128 + tx*8 + j] = make_float4(s1[j], s2[j], mx[j], mn[j]);
    __syncthreads();

    for (int u=t; u<512; u+=256){
        int g = u >> 7, c = u & 127;
        float gmx=-3.4e38f, gmn=3.4e38f;
#pragma unroll
        for (int r=0;r<4;r++){
            float4 v = part[(g*4+r)*128 + c];
            gmx=fmaxf(gmx, v.z); gmn=fminf(gmn, v.w);
        }
        g_pool2[((size_t)blockIdx.x*4 + g)*128 + c] = make_float2(gmx, gmn);
    }
    if (t < 128){
        float ss1=0.f, ss2=0.f;
#pragma unroll
        for (int r=0;r<16;r++){ float4 v = part[r*128+t]; ss1+=v.x; ss2+=v.y; }
        atomicAdd(&g_sum[t],   (double)ss1);
        atomicAdd(&g_sumsq[t], (double)ss2);
    }
}

// =====================================================================
// 7) final pool: out = relu(a * rawmax + c)  (a<0 -> rawmin)
// =====================================================================
__global__ void __launch_bounds__(256) k_pool(float* __restrict__ out)
{
    int idx = blockIdx.x*256 + threadIdx.x;
    int c = idx & 127;
    float2 v = g_pool2[idx];
    float a = g_aff_a[c], cc = g_aff_c[c];
    float raw = (a >= 0.f) ? v.x : v.y;
    out[OUT_XYZ_ELEMS + idx] = fmaxf(fmaf(raw, a, cc), 0.f);
}

// =====================================================================
// launch
// =====================================================================
extern "C" void kernel_launch(void* const* d_in, const int* in_sizes, int n_in,
                              void* d_out, int out_size)
{
    const float* xyz = (const float*)d_in[0];
    const float* pts = (const float*)d_in[1];
    const float* w0  = (const float*)d_in[2];
    const float* b0  = (const float*)d_in[3];
    const float* g0  = (const float*)d_in[4];
    const float* be0 = (const float*)d_in[5];
    const float* w1  = (const float*)d_in[6];
    const float* b1  = (const float*)d_in[7];
    const float* g1  = (const float*)d_in[8];
    const float* be1 = (const float*)d_in[9];
    const float* w2  = (const float*)d_in[10];
    const float* b2  = (const float*)d_in[11];
    const float* g2  = (const float*)d_in[12];
    const float* be2 = (const float*)d_in[13];
    float* out = (float*)d_out;

    float *px0, *px1;
    cudaGetSymbolAddress((void**)&px0, g_x0);
    cudaGetSymbolAddress((void**)&px1, g_x1);

    cudaFuncSetAttribute(k_fps,    cudaFuncAttributeMaxDynamicSharedMemorySize, 139264);
    cudaFuncSetAttribute(k_ballq,  cudaFuncAttributeMaxDynamicSharedMemorySize, 131072);
    cudaFuncSetAttribute(k_layer0, cudaFuncAttributeMaxDynamicSharedMemorySize, 51456);
    cudaFuncSetAttribute(k_layer1, cudaFuncAttributeMaxDynamicSharedMemorySize, 49152);
    cudaFuncSetAttribute(k_layer2, cudaFuncAttributeMaxDynamicSharedMemorySize, 65536);

    k_fps  <<<BB, FPS_THR, 139264>>>(xyz, out);
    k_ballq<<<BB*(SS/64), 256, 131072>>>(xyz, out);
    k_layer0<<<MM/128, 128, 51456>>>(xyz, pts, out, w0, b0);
    k_finalize<<<1,128>>>(g0, be0, 64);
    k_layer1<<<MM/128, 128, 49152>>>(px0, w1, b1, px1);
    k_finalize<<<1,128>>>(g1, be1, 64);
    k_layer2<<<MM/128, 256, 65536>>>(px1, w2, b2);
    k_finalize<<<1,128>>>(g2, be2, 128);
    k_pool <<<(BB*SS*128)/256, 256>>>(out);
}

// round 17
// speedup vs baseline: 1.0518x; 1.0518x over previous
#include <cuda_runtime.h>
#include <math.h>

// ---------------- problem constants ----------------
#define BB    8
#define NN    8192
#define SS    2048
#define KK    32
#define CPTS  64
#define MM    (BB*SS*KK)            // 524288 rows
#define OUT_XYZ_ELEMS (BB*SS*3)     // 49152 floats of new_xyz at front of output

typedef unsigned long long u64;

// ---------------- device scratch ----------------
__device__ int    g_ballidx[MM];
__device__ float  g_x0[(size_t)MM*64];
__device__ float  g_x1[(size_t)MM*64];
__device__ float2 g_pool2[(size_t)BB*SS*128];
__device__ double g_sum[128];      // zero-init at load; k_finalize re-zeroes
__device__ double g_sumsq[128];
__device__ float  g_aff_a[128];
__device__ float  g_aff_c[128];

// ---------------- packed f32x2 helpers ----------------
__device__ __forceinline__ u64 pack2(float lo, float hi){
    u64 r; asm("mov.b64 %0, {%1, %2};" : "=l"(r) : "f"(lo), "f"(hi)); return r;
}
__device__ __forceinline__ u64 dup2(float v){
    u64 r; asm("mov.b64 %0, {%1, %1};" : "=l"(r) : "f"(v)); return r;
}
__device__ __forceinline__ void unpack2(u64 v, float& lo, float& hi){
    asm("mov.b64 {%0, %1}, %2;" : "=f"(lo), "=f"(hi) : "l"(v));
}
__device__ __forceinline__ u64 add2(u64 a, u64 b){
    u64 r; asm("add.rn.f32x2 %0, %1, %2;" : "=l"(r) : "l"(a), "l"(b)); return r;
}
__device__ __forceinline__ u64 mul2(u64 a, u64 b){
    u64 r; asm("mul.rn.f32x2 %0, %1, %2;" : "=l"(r) : "l"(a), "l"(b)); return r;
}
__device__ __forceinline__ u64 fma2(u64 a, u64 b, u64 c){
    u64 r; asm("fma.rn.f32x2 %0, %1, %2, %3;" : "=l"(r) : "l"(a), "l"(b), "l"(c)); return r;
}

// =====================================================================
// 1) FPS with exact geometric pruning (R13 winner, verbatim).
//    256 threads/batch, 32 pts/thread. Lexicographic spatial bucket sort
//    (8x8x8 grid) -> each WARP owns a contiguous 1024-point slab with a
//    warp-reduced bbox. Warp skips its md-update when
//        dmin2(c,bbox)*(1-1e-5) > ub_w   (ub_w = cached warp max-md)
//    which provably (fp margin) cannot change any md -> bit-exact.
//    Tie-break: min ORIGINAL index among bit-equal maxes.
// =====================================================================
#define FPS_THR 256
__global__ void __launch_bounds__(FPS_THR,1) k_fps(const float* __restrict__ xyz,
                                                   float* __restrict__ out)
{
    extern __shared__ __align__(16) unsigned char smraw[];
    float*  sxs   = (float*)smraw;                         // 8192
    float*  sys   = sxs + NN;                              // 8192
    float*  szs   = sys + NN;                              // 8192
    unsigned short* s_fwd = (unsigned short*)(szs + NN);   // 8192 (sortedpos->orig)
    unsigned short* s_inv = s_fwd + NN;                    // 8192 (orig->sortedpos)
    int*      s_hist = (int*)(s_inv + NN);                 // 512
    unsigned* sdist  = (unsigned*)(s_hist + 512);          // 64 (2x32 parity)
    unsigned* sidx   = sdist + 64;                         // 64
    float*    smm    = (float*)(sidx + 64);                // 48 (8 warps x 6)

    int b = blockIdx.x;
    const float* X = xyz + (size_t)b*NN*3;
    int t = threadIdx.x, lane = t & 31, wid = t >> 5;   // wid 0..7

    // ---------------- prologue: load + global min/max + bucket sort ----
    float px[32], py[32], pz[32];
    {
        float mnx=1e30f,mxx=-1e30f,mny=1e30f,mxy=-1e30f,mnz=1e30f,mxz=-1e30f;
#pragma unroll
        for (int i=0;i<32;i++){
            int j = i*256 + t;
            px[i]=X[j*3+0]; py[i]=X[j*3+1]; pz[i]=X[j*3+2];
            mnx=fminf(mnx,px[i]); mxx=fmaxf(mxx,px[i]);
            mny=fminf(mny,py[i]); mxy=fmaxf(mxy,py[i]);
            mnz=fminf(mnz,pz[i]); mxz=fmaxf(mxz,pz[i]);
        }
#pragma unroll
        for (int off=16; off>0; off>>=1){
            mnx=fminf(mnx,__shfl_xor_sync(0xffffffffu,mnx,off));
            mxx=fmaxf(mxx,__shfl_xor_sync(0xffffffffu,mxx,off));
            mny=fminf(mny,__shfl_xor_sync(0xffffffffu,mny,off));
            mxy=fmaxf(mxy,__shfl_xor_sync(0xffffffffu,mxy,off));
            mnz=fminf(mnz,__shfl_xor_sync(0xffffffffu,mnz,off));
            mxz=fmaxf(mxz,__shfl_xor_sync(0xffffffffu,mxz,off));
        }
        if (lane==0){
            smm[wid*6+0]=mnx; smm[wid*6+1]=mxx;
            smm[wid*6+2]=mny; smm[wid*6+3]=mxy;
            smm[wid*6+4]=mnz; smm[wid*6+5]=mxz;
        }
        s_hist[t]=0; s_hist[t+256]=0;
    }
    __syncthreads();

    float gmnx=smm[0],gmxx=smm[1],gmny=smm[2],gmxy=smm[3],gmnz=smm[4],gmxz=smm[5];
#pragma unroll
    for (int w=1;w<8;w++){
        gmnx=fminf(gmnx,smm[w*6+0]); gmxx=fmaxf(gmxx,smm[w*6+1]);
        gmny=fminf(gmny,smm[w*6+2]); gmxy=fmaxf(gmxy,smm[w*6+3]);
        gmnz=fminf(gmnz,smm[w*6+4]); gmxz=fmaxf(gmxz,smm[w*6+5]);
    }
    float rx=gmxx-gmnx, ry=gmxy-gmny, rz=gmxz-gmnz;
    float sclx = (rx>0.f)? 7.9375f/rx : 0.f;
    float scly = (ry>0.f)? 7.9375f/ry : 0.f;
    float sclz = (rz>0.f)? 7.9375f/rz : 0.f;

#pragma unroll
    for (int i=0;i<32;i++){
        int cxq=(int)((px[i]-gmnx)*sclx);
        int cyq=(int)((py[i]-gmny)*scly);
        int czq=(int)((pz[i]-gmnz)*sclz);
        int cell=(cxq<<6)|(cyq<<3)|czq;
        atomicAdd(&s_hist[cell],1);
    }
    __syncthreads();

    // exclusive prefix over 512 bins by warp 0
    if (t < 32){
        int v[16]; int run=0;
#pragma unroll
        for (int k2=0;k2<16;k2++) v[k2]=s_hist[t*16+k2];
#pragma unroll
        for (int k2=0;k2<16;k2++){ int c=v[k2]; v[k2]=run; run+=c; }
        int inc = run;
#pragma unroll
        for (int off=1; off<32; off<<=1){
            int o=__shfl_up_sync(0xffffffffu, inc, off);
            if (lane >= off) inc += o;
        }
        int excl = inc - run;
#pragma unroll
        for (int k2=0;k2<16;k2++) s_hist[t*16+k2]=v[k2]+excl;
    }
    __syncthreads();

    // scatter into sorted arrays
#pragma unroll
    for (int i=0;i<32;i++){
        int cxq=(int)((px[i]-gmnx)*sclx);
        int cyq=(int)((py[i]-gmny)*scly);
        int czq=(int)((pz[i]-gmnz)*sclz);
        int cell=(cxq<<6)|(cyq<<3)|czq;
        int pos = atomicAdd(&s_hist[cell],1);
        sxs[pos]=px[i]; sys[pos]=py[i]; szs[pos]=pz[i];
        int oj = i*256 + t;
        s_fwd[pos]=(unsigned short)oj;
        s_inv[oj]=(unsigned short)pos;
    }
    __syncthreads();

    // reload sorted slab: thread owns positions t*32 .. t*32+31
    u64 cx[16], cy[16], cz[16];
    unsigned oi[16];
    unsigned md[32];
    const unsigned MD_INIT = __float_as_uint(1e10f);
    float bmnx=1e30f,bmxx=-1e30f,bmny=1e30f,bmxy=-1e30f,bmnz=1e30f,bmxz=-1e30f;
#pragma unroll
    for (int q=0;q<16;q++){
        int p0 = t*32 + 2*q;
        float x0=sxs[p0], x1=sxs[p0+1];
        float y0=sys[p0], y1=sys[p0+1];
        float z0=szs[p0], z1=szs[p0+1];
        cx[q]=pack2(x0,x1); cy[q]=pack2(y0,y1); cz[q]=pack2(z0,z1);
        unsigned lo=s_fwd[p0], hi=s_fwd[p0+1];
        oi[q] = lo | (hi<<16);
        md[2*q]=MD_INIT; md[2*q+1]=MD_INIT;
        bmnx=fminf(bmnx,fminf(x0,x1)); bmxx=fmaxf(bmxx,fmaxf(x0,x1));
        bmny=fminf(bmny,fminf(y0,y1)); bmxy=fmaxf(bmxy,fmaxf(y0,y1));
        bmnz=fminf(bmnz,fminf(z0,z1)); bmxz=fmaxf(bmxz,fmaxf(z0,z1));
    }
#pragma unroll
    for (int off=16; off>0; off>>=1){
        bmnx=fminf(bmnx,__shfl_xor_sync(0xffffffffu,bmnx,off));
        bmxx=fmaxf(bmxx,__shfl_xor_sync(0xffffffffu,bmxx,off));
        bmny=fminf(bmny,__shfl_xor_sync(0xffffffffu,bmny,off));
        bmxy=fmaxf(bmxy,__shfl_xor_sync(0xffffffffu,bmxy,off));
        bmnz=fminf(bmnz,__shfl_xor_sync(0xffffffffu,bmnz,off));
        bmxz=fmaxf(bmxz,__shfl_xor_sync(0xffffffffu,bmxz,off));
    }
    if (t < 64){
        int half = t >> 5, slot = t & 31;
        if (slot >= 8){
            sdist[half*32 + slot] = 0u;
            sidx [half*32 + slot] = 0xffffffffu;
        }
    }
    unsigned cached_rmax = MD_INIT;
    unsigned cached_jw   = 0u;
    __syncthreads();

    float lx=X[0], ly=X[1], lz=X[2];
    float* onew = out + (size_t)b*SS*3;

    for (int s=0;s<SS;s++){
        if (t==0){ onew[s*3+0]=lx; onew[s*3+1]=ly; onew[s*3+2]=lz; }

        float ddx = fmaxf(fmaxf(bmnx-lx, lx-bmxx), 0.0f);
        float ddy = fmaxf(fmaxf(bmny-ly, ly-bmxy), 0.0f);
        float ddz = fmaxf(fmaxf(bmnz-lz, lz-bmxz), 0.0f);
        float dmin2 = __fmaf_rn(ddx,ddx,__fmaf_rn(ddy,ddy,__fmul_rn(ddz,ddz)));
        bool doupd = !(dmin2 * 0.99999f > __uint_as_float(cached_rmax));

        unsigned rmax_w, jwor;
        if (doupd){
            u64 nlx=dup2(-lx), nly=dup2(-ly), nlz=dup2(-lz);
#pragma unroll
            for (int q=0;q<16;q++){
                u64 dx=add2(cx[q],nlx);
                u64 dy=add2(cy[q],nly);
                u64 dz=add2(cz[q],nlz);
                u64 dd=fma2(dz,dz,fma2(dy,dy,mul2(dx,dx)));
                float d0,d1; unpack2(dd,d0,d1);
                md[2*q]   = umin(md[2*q],   __float_as_uint(d0));
                md[2*q+1] = umin(md[2*q+1], __float_as_uint(d1));
            }
            unsigned g2_[16];
#pragma unroll
            for (int i=0;i<16;i++) g2_[i]=umax(md[2*i],md[2*i+1]);
            unsigned g4_[8];
#pragma unroll
            for (int i=0;i<8;i++) g4_[i]=umax(g2_[2*i],g2_[2*i+1]);
            unsigned g8a=umax(g4_[0],g4_[1]), g8b=umax(g4_[2],g4_[3]);
            unsigned g8c=umax(g4_[4],g4_[5]), g8d=umax(g4_[6],g4_[7]);
            unsigned bvu=umax(umax(g8a,g8b),umax(g8c,g8d));

            unsigned m8[8];
#pragma unroll
            for (int q=0;q<16;q+=2){
                unsigned lo0=oi[q]&0xffffu,   hi0=oi[q]>>16;
                unsigned lo1=oi[q+1]&0xffffu, hi1=oi[q+1]>>16;
                unsigned a=(md[2*q]==bvu)  ? lo0 : 0xffffu;
                unsigned bq=(md[2*q+1]==bvu)? hi0 : 0xffffu;
                unsigned c=(md[2*q+2]==bvu)? lo1 : 0xffffu;
                unsigned d=(md[2*q+3]==bvu)? hi1 : 0xffffu;
                m8[q>>1]=umin(umin(a,bq),umin(c,d));
            }
            unsigned mo = umin(umin(umin(m8[0],m8[1]),umin(m8[2],m8[3])),
                               umin(umin(m8[4],m8[5]),umin(m8[6],m8[7])));

            rmax_w = __reduce_max_sync(0xffffffffu, bvu);
            unsigned cand = (bvu==rmax_w) ? mo : 0xffffffffu;
            jwor   = __reduce_min_sync(0xffffffffu, cand);
            cached_rmax = rmax_w; cached_jw = jwor;
        } else {
            rmax_w = cached_rmax; jwor = cached_jw;
        }

        int pb = (s & 1) * 32;
        if (lane==0){ sdist[pb + wid] = rmax_w; sidx[pb + wid] = jwor; }
        __syncthreads();

        unsigned d2v = sdist[pb + lane];
        unsigned i2v = sidx [pb + lane];
        unsigned gmax = __reduce_max_sync(0xffffffffu, d2v);
        unsigned c2   = (d2v==gmax) ? i2v : 0xffffffffu;
        unsigned jo   = __reduce_min_sync(0xffffffffu, c2);

        int pos = (int)s_inv[jo];
        lx = sxs[pos]; ly = sys[pos]; lz = szs[pos];
    }
}

// =====================================================================
// 2) Ball query: 64 points per loop iteration (two 32-pt halves processed
//    strictly in index order -> identical first-K/pad semantics).
// =====================================================================
__global__ void __launch_bounds__(256,1) k_ballq(const float* __restrict__ xyz,
                                                 const float* __restrict__ newxyz)
{
    extern __shared__ __align__(16) unsigned char s_raw[];
    float4* sp = (float4*)s_raw;

    int b     = blockIdx.x >> 5;
    int sbase = (blockIdx.x & 31) * 64;
    const float* X = xyz + (size_t)b*NN*3;

    for (int j=threadIdx.x; j<NN; j+=256){
        float x=X[j*3+0], y=X[j*3+1], z=X[j*3+2];
        float pp=__fmaf_rn(z,z,__fmaf_rn(y,y,__fmul_rn(x,x)));
        sp[j]=make_float4(x,y,z,pp);
    }
    __syncthreads();

    int wid=threadIdx.x>>5, lane=threadIdx.x&31;
    for (int ci=0; ci<8; ci++){
        int s = sbase + wid*8 + ci;
        const float* q = newxyz + ((size_t)b*SS + s)*3;
        float qx=q[0], qy=q[1], qz=q[2];
        float qq=__fmaf_rn(qz,qz,__fmaf_rn(qy,qy,__fmul_rn(qx,qx)));
        int* o = g_ballidx + ((size_t)b*SS + s)*KK;
        int cnt=0, first=0; bool havefirst=false;

        for (int base=0; base<NN; base+=64){
            float4 pA = sp[base+lane];
            float4 pB = sp[base+32+lane];
            float dotA=__fmaf_rn(qz,pA.z,__fmaf_rn(qy,pA.y,__fmul_rn(qx,pA.x)));
            float d2A =__fmaf_rn(-2.0f,dotA,__fadd_rn(qq,pA.w));
            float dotB=__fmaf_rn(qz,pB.z,__fmaf_rn(qy,pB.y,__fmul_rn(qx,pB.x)));
            float d2B =__fmaf_rn(-2.0f,dotB,__fadd_rn(qq,pB.w));
            bool vA = (d2A <= 0.0625f);
            bool vB = (d2B <= 0.0625f);
            unsigned mA = __ballot_sync(0xffffffffu, vA);
            unsigned mB = __ballot_sync(0xffffffffu, vB);
            if (mA){
                if (!havefirst){ first = base + (__ffs(mA)-1); havefirst=true; }
                int pre = __popc(mA & ((1u<<lane)-1u));
                if (vA && (cnt+pre) < KK) o[cnt+pre] = base+lane;
                cnt += __popc(mA);
            }
            if (mB && cnt < KK){
                if (!havefirst){ first = base + 32 + (__ffs(mB)-1); havefirst=true; }
                int pre = __popc(mB & ((1u<<lane)-1u));
                if (vB && (cnt+pre) < KK) o[cnt+pre] = base+32+lane;
                cnt += __popc(mB);
            } else if (mB){
                cnt += __popc(mB);
            }
            if (cnt >= KK) break;
        }
        if (cnt < KK){
            for (int p=cnt+lane; p<KK; p+=32) o[p]=first;
        }
    }
}

// =====================================================================
// 3) stats finalize
// =====================================================================
__global__ void k_finalize(const float* __restrict__ g, const float* __restrict__ be, int C)
{
    int c = threadIdx.x;
    if (c < C){
        double mean = g_sum[c]   * (1.0/(double)MM);
        double var  = g_sumsq[c] * (1.0/(double)MM) - mean*mean;
        double a = (double)g[c] / sqrt(var + 1e-5);
        g_aff_a[c] = (float)a;
        g_aff_c[c] = (float)((double)be[c] - mean*a);
        g_sum[c]=0.0; g_sumsq[c]=0.0;
    }
}

// =====================================================================
// 4) layer 0: gather + GEMM [128 rows x 64 cols], K=67, f32x2 row-pair packed.
// =====================================================================
__global__ void __launch_bounds__(128) k_layer0(const float* __restrict__ xyz,
                                                const float* __restrict__ pts,
                                                const float* __restrict__ newxyz,
                                                const float* __restrict__ w0,
                                                const float* __restrict__ b0)
{
    extern __shared__ __align__(16) unsigned char s_raw[];
    u64*   sfP = (u64*)s_raw;                       // [67][64] pairs, k-major
    float* sw  = (float*)(s_raw + 67*64*8);         // [67][64] k-major
    int t = threadIdx.x;
    size_t row0 = (size_t)blockIdx.x * 128;

    for (int i=t; i<67*64; i+=128){
        int o = i/67, c = i%67;
        int cp = (c>=3) ? (c-3) : (64+c);
        sw[cp*64+o] = w0[i];
    }
    {
        int p = t & 63, h = t >> 6;
        size_t r0g = row0 + 2*p, r1g = r0g + 1;
        int bs = (int)(r0g >> 5);
        int b  = bs >> 11;
        int n0 = g_ballidx[r0g], n1 = g_ballidx[r1g];
        const float4* ra = (const float4*)(pts + ((size_t)b*NN + n0)*CPTS) + h*8;
        const float4* rb = (const float4*)(pts + ((size_t)b*NN + n1)*CPTS) + h*8;
        int c0 = h*32;
#pragma unroll
        for (int v=0; v<8; v++){
            float4 a = ra[v], b4 = rb[v];
            int c = c0 + v*4;
            sfP[(c+0)*64+p]=pack2(a.x,b4.x);
            sfP[(c+1)*64+p]=pack2(a.y,b4.y);
            sfP[(c+2)*64+p]=pack2(a.z,b4.z);
            sfP[(c+3)*64+p]=pack2(a.w,b4.w);
        }
        if (h==0){
            const float* p3a = xyz + ((size_t)b*NN + n0)*3;
            const float* p3b = xyz + ((size_t)b*NN + n1)*3;
            const float* c3  = newxyz + (size_t)bs*3;
            sfP[64*64+p]=pack2(p3a[0]-c3[0], p3b[0]-c3[0]);
            sfP[65*64+p]=pack2(p3a[1]-c3[1], p3b[1]-c3[1]);
            sfP[66*64+p]=pack2(p3a[2]-c3[2], p3b[2]-c3[2]);
        }
    }
    __syncthreads();

    int tx = t & 7, tp = t >> 3;
    u64 acc[4][8];
#pragma unroll
    for (int i=0;i<4;i++)
#pragma unroll
        for (int j=0;j<8;j++) acc[i][j]=0ull;

    for (int k=0;k<64;k+=4){
#pragma unroll
        for (int kk=0;kk<4;kk++){
            const u64* arow = sfP + (size_t)(k+kk)*64 + tp*4;
            ulonglong2 v0 = *(const ulonglong2*)arow;
            ulonglong2 v1 = *(const ulonglong2*)(arow+2);
            const float4* brow = (const float4*)(sw + (size_t)(k+kk)*64 + tx*8);
            float4 b0v=brow[0], b1v=brow[1];
            u64 bb[8];
            bb[0]=dup2(b0v.x); bb[1]=dup2(b0v.y); bb[2]=dup2(b0v.z); bb[3]=dup2(b0v.w);
            bb[4]=dup2(b1v.x); bb[5]=dup2(b1v.y); bb[6]=dup2(b1v.z); bb[7]=dup2(b1v.w);
            u64 a0=v0.x,a1=v0.y,a2=v1.x,a3=v1.y;
#pragma unroll
            for (int j=0;j<8;j++){
                acc[0][j]=fma2(a0,bb[j],acc[0][j]);
                acc[1][j]=fma2(a1,bb[j],acc[1][j]);
                acc[2][j]=fma2(a2,bb[j],acc[2][j]);
                acc[3][j]=fma2(a3,bb[j],acc[3][j]);
            }
        }
    }
#pragma unroll
    for (int k=64;k<67;k++){
        const u64* arow = sfP + (size_t)k*64 + tp*4;
        ulonglong2 v0 = *(const ulonglong2*)arow;
        ulonglong2 v1 = *(const ulonglong2*)(arow+2);
        const float4* brow = (const float4*)(sw + (size_t)k*64 + tx*8);
        float4 b0v=brow[0], b1v=brow[1];
        u64 bb[8];
        bb[0]=dup2(b0v.x); bb[1]=dup2(b0v.y); bb[2]=dup2(b0v.z); bb[3]=dup2(b0v.w);
        bb[4]=dup2(b1v.x); bb[5]=dup2(b1v.y); bb[6]=dup2(b1v.z); bb[7]=dup2(b1v.w);
        u64 a0=v0.x,a1=v0.y,a2=v1.x,a3=v1.y;
#pragma unroll
        for (int j=0;j<8;j++){
            acc[0][j]=fma2(a0,bb[j],acc[0][j]);
            acc[1][j]=fma2(a1,bb[j],acc[1][j]);
            acc[2][j]=fma2(a2,bb[j],acc[2][j]);
            acc[3][j]=fma2(a3,bb[j],acc[3][j]);
        }
    }

    u64 bP[8];
    {
        float4 b0v = *(const float4*)&b0[tx*8];
        float4 b1v = *(const float4*)&b0[tx*8+4];
        bP[0]=dup2(b0v.x); bP[1]=dup2(b0v.y); bP[2]=dup2(b0v.z); bP[3]=dup2(b0v.w);
        bP[4]=dup2(b1v.x); bP[5]=dup2(b1v.y); bP[6]=dup2(b1v.z); bP[7]=dup2(b1v.w);
    }
    float s1[8], s2[8];
#pragma unroll
    for (int j=0;j<8;j++){ s1[j]=0.f; s2[j]=0.f; }
#pragma unroll
    for (int i=0;i<4;i++){
        size_t ra = row0 + (size_t)(tp*4+i)*2;
        float lo[8], hi[8];
#pragma unroll
        for (int j=0;j<8;j++){
            u64 v = add2(acc[i][j], bP[j]);
            unpack2(v, lo[j], hi[j]);
            s1[j]+=lo[j]; s1[j]+=hi[j];
            s2[j]=fmaf(lo[j],lo[j],s2[j]); s2[j]=fmaf(hi[j],hi[j],s2[j]);
        }
        *(float4*)&g_x0[ra*64 + tx*8]       = make_float4(lo[0],lo[1],lo[2],lo[3]);
        *(float4*)&g_x0[ra*64 + tx*8 + 4]   = make_float4(lo[4],lo[5],lo[6],lo[7]);
        *(float4*)&g_x0[(ra+1)*64 + tx*8]   = make_float4(hi[0],hi[1],hi[2],hi[3]);
        *(float4*)&g_x0[(ra+1)*64 + tx*8+4] = make_float4(hi[4],hi[5],hi[6],hi[7]);
    }
    __syncthreads();
    float2* part = (float2*)s_raw;   // [16][64]
#pragma unroll
    for (int j=0;j<8;j++) part[tp*64 + tx*8 + j] = make_float2(s1[j], s2[j]);
    __syncthreads();
    if (t < 64){
        float ss1=0.f, ss2=0.f;
#pragma unroll
        for (int r=0;r<16;r++){ float2 v = part[r*64+t]; ss1+=v.x; ss2+=v.y; }
        atomicAdd(&g_sum[t],   (double)ss1);
        atomicAdd(&g_sumsq[t], (double)ss2);
    }
}

// =====================================================================
// 5) layer 1: relu(affine(x0)) @ W^T + b, 128x64 tile, f32x2 packed
// =====================================================================
__global__ void __launch_bounds__(128) k_layer1(const float* __restrict__ xin,
                                                const float* __restrict__ w,
                                                const float* __restrict__ bias,
                                                float* __restrict__ xout)
{
    extern __shared__ __align__(16) unsigned char s_raw[];
    u64*   sfP = (u64*)s_raw;                       // [64][64]
    float* sw  = (float*)(s_raw + 64*64*8);         // [64][64]
    int t = threadIdx.x;
    size_t row0 = (size_t)blockIdx.x * 128;

    for (int i=t; i<64*64; i+=128){
        int o=i>>6, c=i&63;
        sw[c*64+o] = w[i];
    }
    {
        int p = t & 63, h = t >> 6;
        const float4* ra = (const float4*)(xin + (row0 + 2*p)*64) + h*8;
        const float4* rb = (const float4*)(xin + (row0 + 2*p+1)*64) + h*8;
        int c0 = h*32;
#pragma unroll
        for (int v=0; v<8; v++){
            float4 a = ra[v], b4 = rb[v];
            int c = c0 + v*4;
            float a0=fmaxf(fmaf(a.x, g_aff_a[c+0], g_aff_c[c+0]),0.f);
            float a1=fmaxf(fmaf(a.y, g_aff_a[c+1], g_aff_c[c+1]),0.f);
            float a2=fmaxf(fmaf(a.z, g_aff_a[c+2], g_aff_c[c+2]),0.f);
            float a3=fmaxf(fmaf(a.w, g_aff_a[c+3], g_aff_c[c+3]),0.f);
            float b0=fmaxf(fmaf(b4.x,g_aff_a[c+0], g_aff_c[c+0]),0.f);
            float b1=fmaxf(fmaf(b4.y,g_aff_a[c+1], g_aff_c[c+1]),0.f);
            float b2=fmaxf(fmaf(b4.z,g_aff_a[c+2], g_aff_c[c+2]),0.f);
            float b3=fmaxf(fmaf(b4.w,g_aff_a[c+3], g_aff_c[c+3]),0.f);
            sfP[(c+0)*64+p]=pack2(a0,b0);
            sfP[(c+1)*64+p]=pack2(a1,b1);
            sfP[(c+2)*64+p]=pack2(a2,b2);
            sfP[(c+3)*64+p]=pack2(a3,b3);
        }
    }
    __syncthreads();

    int tx = t & 7, tp = t >> 3;
    u64 acc[4][8];
#pragma unroll
    for (int i=0;i<4;i++)
#pragma unroll
        for (int j=0;j<8;j++) acc[i][j]=0ull;

    for (int k=0;k<64;k+=4){
#pragma unroll
        for (int kk=0;kk<4;kk++){
            const u64* arow = sfP + (size_t)(k+kk)*64 + tp*4;
            ulonglong2 v0 = *(const ulonglong2*)arow;
            ulonglong2 v1 = *(const ulonglong2*)(arow+2);
            const float4* brow = (const float4*)(sw + (size_t)(k+kk)*64 + tx*8);
            float4 b0v=brow[0], b1v=brow[1];
            u64 bb[8];
            bb[0]=dup2(b0v.x); bb[1]=dup2(b0v.y); bb[2]=dup2(b0v.z); bb[3]=dup2(b0v.w);
            bb[4]=dup2(b1v.x); bb[5]=dup2(b1v.y); bb[6]=dup2(b1v.z); bb[7]=dup2(b1v.w);
            u64 a0=v0.x,a1=v0.y,a2=v1.x,a3=v1.y;
#pragma unroll
            for (int j=0;j<8;j++){
                acc[0][j]=fma2(a0,bb[j],acc[0][j]);
                acc[1][j]=fma2(a1,bb[j],acc[1][j]);
                acc[2][j]=fma2(a2,bb[j],acc[2][j]);
                acc[3][j]=fma2(a3,bb[j],acc[3][j]);
            }
        }
    }

    u64 bP[8];
    {
        float4 b0v = *(const float4*)&bias[tx*8];
        float4 b1v = *(const float4*)&bias[tx*8+4];
        bP[0]=dup2(b0v.x); bP[1]=dup2(b0v.y); bP[2]=dup2(b0v.z); bP[3]=dup2(b0v.w);
        bP[4]=dup2(b1v.x); bP[5]=dup2(b1v.y); bP[6]=dup2(b1v.z); bP[7]=dup2(b1v.w);
    }
    float s1[8], s2[8];
#pragma unroll
    for (int j=0;j<8;j++){ s1[j]=0.f; s2[j]=0.f; }
#pragma unroll
    for (int i=0;i<4;i++){
        size_t ra = row0 + (size_t)(tp*4+i)*2;
        float lo[8], hi[8];
#pragma unroll
        for (int j=0;j<8;j++){
            u64 v = add2(acc[i][j], bP[j]);
            unpack2(v, lo[j], hi[j]);
            s1[j]+=lo[j]; s1[j]+=hi[j];
            s2[j]=fmaf(lo[j],lo[j],s2[j]); s2[j]=fmaf(hi[j],hi[j],s2[j]);
        }
        *(float4*)&xout[ra*64 + tx*8]       = make_float4(lo[0],lo[1],lo[2],lo[3]);
        *(float4*)&xout[ra*64 + tx*8 + 4]   = make_float4(lo[4],lo[5],lo[6],lo[7]);
        *(float4*)&xout[(ra+1)*64 + tx*8]   = make_float4(hi[0],hi[1],hi[2],hi[3]);
        *(float4*)&xout[(ra+1)*64 + tx*8+4] = make_float4(hi[4],hi[5],hi[6],hi[7]);
    }
    __syncthreads();
    float2* part = (float2*)s_raw;
#pragma unroll
    for (int j=0;j<8;j++) part[tp*64 + tx*8 + j] = make_float2(s1[j], s2[j]);
    __syncthreads();
    if (t < 64){
        float ss1=0.f, ss2=0.f;
#pragma unroll
        for (int r=0;r<16;r++){ float2 v = part[r*64+t]; ss1+=v.x; ss2+=v.y; }
        atomicAdd(&g_sum[t],   (double)ss1);
        atomicAdd(&g_sumsq[t], (double)ss2);
    }
}

// =====================================================================
// 6) layer 2: relu(affine(x1)) @ W^T + b, 128x128 tile, f32x2 packed.
// =====================================================================
__global__ void __launch_bounds__(256) k_layer2(const float* __restrict__ xin,
                                                const float* __restrict__ w,
                                                const float* __restrict__ bias)
{
    extern __shared__ __align__(16) unsigned char s_raw[];
    u64*   sfP = (u64*)s_raw;                       // [64][64]  32KB
    float* sw  = (float*)(s_raw + 64*64*8);         // [64][128] 32KB
    int t = threadIdx.x;
    size_t row0 = (size_t)blockIdx.x * 128;

    for (int i=t; i<128*64; i+=256){
        int o=i>>6, c=i&63;
        sw[c*128+o] = w[i];
    }
    {
        int p = t & 63, q = t >> 6;
        const float4* ra = (const float4*)(xin + (row0 + 2*p)*64) + q*4;
        const float4* rb = (const float4*)(xin + (row0 + 2*p+1)*64) + q*4;
        int c0 = q*16;
#pragma unroll
        for (int v=0; v<4; v++){
            float4 a = ra[v], b4 = rb[v];
            int c = c0 + v*4;
            float a0=fmaxf(fmaf(a.x, g_aff_a[c+0], g_aff_c[c+0]),0.f);
            float a1=fmaxf(fmaf(a.y, g_aff_a[c+1], g_aff_c[c+1]),0.f);
            float a2=fmaxf(fmaf(a.z, g_aff_a[c+2], g_aff_c[c+2]),0.f);
            float a3=fmaxf(fmaf(a.w, g_aff_a[c+3], g_aff_c[c+3]),0.f);
            float b0=fmaxf(fmaf(b4.x,g_aff_a[c+0], g_aff_c[c+0]),0.f);
            float b1=fmaxf(fmaf(b4.y,g_aff_a[c+1], g_aff_c[c+1]),0.f);
            float b2=fmaxf(fmaf(b4.z,g_aff_a[c+2], g_aff_c[c+2]),0.f);
            float b3=fmaxf(fmaf(b4.w,g_aff_a[c+3], g_aff_c[c+3]),0.f);
            sfP[(c+0)*64+p]=pack2(a0,b0);
            sfP[(c+1)*64+p]=pack2(a1,b1);
            sfP[(c+2)*64+p]=pack2(a2,b2);
            sfP[(c+3)*64+p]=pack2(a3,b3);
        }
    }
    __syncthreads();

    int tx = t & 15, tp = t >> 4;
    u64 acc[4][8];
#pragma unroll
    for (int i=0;i<4;i++)
#pragma unroll
        for (int j=0;j<8;j++) acc[i][j]=0ull;

    for (int k=0;k<64;k+=4){
#pragma unroll
        for (int kk=0;kk<4;kk++){
            const u64* arow = sfP + (size_t)(k+kk)*64 + tp*4;
            ulonglong2 v0 = *(const ulonglong2*)arow;
            ulonglong2 v1 = *(const ulonglong2*)(arow+2);
            const float4* brow = (const float4*)(sw + (size_t)(k+kk)*128 + tx*8);
            float4 b0v=brow[0], b1v=brow[1];
            u64 bb[8];
            bb[0]=dup2(b0v.x); bb[1]=dup2(b0v.y); bb[2]=dup2(b0v.z); bb[3]=dup2(b0v.w);
            bb[4]=dup2(b1v.x); bb[5]=dup2(b1v.y); bb[6]=dup2(b1v.z); bb[7]=dup2(b1v.w);
            u64 a0=v0.x,a1=v0.y,a2=v1.x,a3=v1.y;
#pragma unroll
            for (int j=0;j<8;j++){
                acc[0][j]=fma2(a0,bb[j],acc[0][j]);
                acc[1][j]=fma2(a1,bb[j],acc[1][j]);
                acc[2][j]=fma2(a2,bb[j],acc[2][j]);
                acc[3][j]=fma2(a3,bb[j],acc[3][j]);
            }
        }
    }

    u64 bP[8];
    {
        float4 b0v = *(const float4*)&bias[tx*8];
        float4 b1v = *(const float4*)&bias[tx*8+4];
        bP[0]=dup2(b0v.x); bP[1]=dup2(b0v.y); bP[2]=dup2(b0v.z); bP[3]=dup2(b0v.w);
        bP[4]=dup2(b1v.x); bP[5]=dup2(b1v.y); bP[6]=dup2(b1v.z); bP[7]=dup2(b1v.w);
    }
    float s1[8], s2[8], mx[8], mn[8];
#pragma unroll
    for (int j=0;j<8;j++){ s1[j]=0.f; s2[j]=0.f; mx[j]=-3.4e38f; mn[j]=3.4e38f; }
#pragma unroll
    for (int i=0;i<4;i++){
#pragma unroll
        for (int j=0;j<8;j++){
            u64 v = add2(acc[i][j], bP[j]);
            float lo, hi; unpack2(v, lo, hi);
            s1[j]+=lo; s1[j]+=hi;
            s2[j]=fmaf(lo,lo,s2[j]); s2[j]=fmaf(hi,hi,s2[j]);
            mx[j]=fmaxf(mx[j], fmaxf(lo,hi));
            mn[j]=fminf(mn[j], fminf(lo,hi));
        }
    }
    __syncthreads();
    float4* part = (float4*)s_raw;   // [16][128] = 32KB
#pragma unroll
    for (int j=0;j<8;j++) part[tp*128 + tx*8 + j] = make_float4(s1[j], s2[j], mx[j], mn[j]);
    __syncthreads();

    for (int u=t; u<512; u+=256){
        int g = u >> 7, c = u & 127;
        float gmx=-3.4e38f, gmn=3.4e38f;
#pragma unroll
        for (int r=0;r<4;r++){
            float4 v = part[(g*4+r)*128 + c];
            gmx=fmaxf(gmx, v.z); gmn=fminf(gmn, v.w);
        }
        g_pool2[((size_t)blockIdx.x*4 + g)*128 + c] = make_float2(gmx, gmn);
    }
    if (t < 128){
        float ss1=0.f, ss2=0.f;
#pragma unroll
        for (int r=0;r<16;r++){ float4 v = part[r*128+t]; ss1+=v.x; ss2+=v.y; }
        atomicAdd(&g_sum[t],   (double)ss1);
        atomicAdd(&g_sumsq[t], (double)ss2);
    }
}

// =====================================================================
// 7) final pool: out = relu(a * rawmax + c)  (a<0 -> rawmin)
// =====================================================================
__global__ void __launch_bounds__(256) k_pool(float* __restrict__ out)
{
    int idx = blockIdx.x*256 + threadIdx.x;
    int c = idx & 127;
    float2 v = g_pool2[idx];
    float a = g_aff_a[c], cc = g_aff_c[c];
    float raw = (a >= 0.f) ? v.x : v.y;
    out[OUT_XYZ_ELEMS + idx] = fmaxf(fmaf(raw, a, cc), 0.f);
}

// =====================================================================
// launch
// =====================================================================
extern "C" void kernel_launch(void* const* d_in, const int* in_sizes, int n_in,
                              void* d_out, int out_size)
{
    const float* xyz = (const float*)d_in[0];
    const float* pts = (const float*)d_in[1];
    const float* w0  = (const float*)d_in[2];
    const float* b0  = (const float*)d_in[3];
    const float* g0  = (const float*)d_in[4];
    const float* be0 = (const float*)d_in[5];
    const float* w1  = (const float*)d_in[6];
    const float* b1  = (const float*)d_in[7];
    const float* g1  = (const float*)d_in[8];
    const float* be1 = (const float*)d_in[9];
    const float* w2  = (const float*)d_in[10];
    const float* b2  = (const float*)d_in[11];
    const float* g2  = (const float*)d_in[12];
    const float* be2 = (const float*)d_in[13];
    float* out = (float*)d_out;

    float *px0, *px1;
    cudaGetSymbolAddress((void**)&px0, g_x0);
    cudaGetSymbolAddress((void**)&px1, g_x1);

    cudaFuncSetAttribute(k_fps,    cudaFuncAttributeMaxDynamicSharedMemorySize, 139264);
    cudaFuncSetAttribute(k_ballq,  cudaFuncAttributeMaxDynamicSharedMemorySize, 131072);
    cudaFuncSetAttribute(k_layer0, cudaFuncAttributeMaxDynamicSharedMemorySize, 51456);
    cudaFuncSetAttribute(k_layer1, cudaFuncAttributeMaxDynamicSharedMemorySize, 49152);
    cudaFuncSetAttribute(k_layer2, cudaFuncAttributeMaxDynamicSharedMemorySize, 65536);

    k_fps  <<<BB, FPS_THR, 139264>>>(xyz, out);
    k_ballq<<<BB*(SS/64), 256, 131072>>>(xyz, out);
    k_layer0<<<MM/128, 128, 51456>>>(xyz, pts, out, w0, b0);
    k_finalize<<<1,128>>>(g0, be0, 64);
    k_layer1<<<MM/128, 128, 49152>>>(px0, w1, b1, px1);
    k_finalize<<<1,128>>>(g1, be1, 64);
    k_layer2<<<MM/128, 256, 65536>>>(px1, w2, b2);
    k_finalize<<<1,128>>>(g2, be2, 128);
    k_pool <<<(BB*SS*128)/256, 256>>>(out);
}